// round 1
// baseline (speedup 1.0000x reference)
#include <cuda_runtime.h>

// Quantum autoencoder forward, batch=256.
// Key reductions vs reference:
//  - wires 10..13 never evolve before the swap test -> simulate only 10 qubits (1024 amps)
//  - swap test with |000> reference register collapses to
//        P(aux=1) = 0.5 * (1 - sum_{trash bits = 000} |amp|^2)
//  - AngleEmbedding on |0..0> is a product state -> direct init
//
// Layout: one warp per sample. Global 10-bit index g = lane*32 + j.
// Wire w (PennyLane wire 0 = MSB) -> bit (9-w).
//   wires 0..4  -> bits 9..5 = lane bits 4..0  (gates via __shfl_xor_sync)
//   wires 5..9  -> bits 4..0 = local bits 4..0 (gates purely in registers)

#define NUM_Q 10
#define DEPTH 4
#define BATCH 256
#define FULLM 0xFFFFFFFFu

__global__ void __launch_bounds__(128, 1)
qae_kernel(const float* __restrict__ features,
           const float* __restrict__ weights,
           float* __restrict__ out)
{
    const int warp_id = (blockIdx.x * blockDim.x + threadIdx.x) >> 5;
    const int lane = threadIdx.x & 31;
    if (warp_id >= BATCH) return;

    const float* f = features + warp_id * NUM_Q;

    // ---- Embedding as product state: amp[g] = prod_w (bit? sin : cos)(f_w/2) * (-i)^popc(g)
    float fc[NUM_Q], fs[NUM_Q];
#pragma unroll
    for (int w = 0; w < NUM_Q; ++w) {
        float sv, cv;
        sincosf(0.5f * f[w], &sv, &cv);
        fc[w] = cv; fs[w] = sv;
    }

    float re[32], im[32];
#pragma unroll
    for (int j = 0; j < 32; ++j) {
        const int g = (lane << 5) | j;
        float r = 1.0f;
#pragma unroll
        for (int w = 0; w < NUM_Q; ++w) {
            const int bit = 9 - w;
            r *= ((g >> bit) & 1) ? fs[w] : fc[w];
        }
        const int k = __popc(g) & 3;   // (-i)^k
        re[j] = (k == 0) ? r : (k == 2 ? -r : 0.0f);
        im[j] = (k == 1) ? -r : (k == 3 ? r : 0.0f);
    }

    // ---- BasicEntanglerLayers
    for (int l = 0; l < DEPTH; ++l) {
        float c[NUM_Q], s[NUM_Q];
#pragma unroll
        for (int w = 0; w < NUM_Q; ++w) {
            float sv, cv;
            sincosf(0.5f * weights[l * NUM_Q + w], &sv, &cv);
            c[w] = cv; s[w] = sv;
        }

        // RX on wires 0..4 (lane bits 4..0): symmetric matrix, pure shfl form
        //   new = c*mine + (-i s)*partner  -> re += s*p_im ; im -= s*p_re
#pragma unroll
        for (int w = 0; w < 5; ++w) {
            const int m = 1 << (4 - w);
            const float cw = c[w], sw = s[w];
#pragma unroll
            for (int j = 0; j < 32; ++j) {
                const float pr = __shfl_xor_sync(FULLM, re[j], m);
                const float pi = __shfl_xor_sync(FULLM, im[j], m);
                const float nr = cw * re[j] + sw * pi;
                const float ni = cw * im[j] - sw * pr;
                re[j] = nr; im[j] = ni;
            }
        }

        // RX on wires 5..9 (local bits 4..0)
#pragma unroll
        for (int w = 5; w < 10; ++w) {
            const int b = 9 - w;
            const float cw = c[w], sw = s[w];
#pragma unroll
            for (int j = 0; j < 32; ++j) {
                if (j & (1 << b)) continue;      // compile-time predicate (unrolled)
                const int k2 = j | (1 << b);
                const float ar = re[j], ai = im[j];
                const float br = re[k2], bi = im[k2];
                re[j]  = cw * ar + sw * bi;
                im[j]  = cw * ai - sw * br;
                re[k2] = cw * br + sw * ai;
                im[k2] = cw * bi - sw * ar;
            }
        }

        // Ring CNOTs: CNOT(w, w+1 mod 10)
        // w=0..3: control lane bit (4-w), target lane bit (3-w)
#pragma unroll
        for (int w = 0; w < 4; ++w) {
            const int cb = 4 - w;
            const int tm = 1 << (3 - w);
            const bool ctrl = (lane >> cb) & 1;
#pragma unroll
            for (int j = 0; j < 32; ++j) {
                const float pr = __shfl_xor_sync(FULLM, re[j], tm);
                const float pi = __shfl_xor_sync(FULLM, im[j], tm);
                if (ctrl) { re[j] = pr; im[j] = pi; }
            }
        }

        // w=4: control = lane bit 0, target = local bit 4 (conditional local swap)
        {
            const bool ctrl = lane & 1;
#pragma unroll
            for (int j = 0; j < 16; ++j) {
                const int k2 = j | 16;
                if (ctrl) {
                    float t;
                    t = re[j]; re[j] = re[k2]; re[k2] = t;
                    t = im[j]; im[j] = im[k2]; im[k2] = t;
                }
            }
        }

        // w=5..8: both local: control bit (9-w), target bit (8-w)
#pragma unroll
        for (int w = 5; w < 9; ++w) {
            const int cb = 9 - w;
            const int tb = 8 - w;
#pragma unroll
            for (int j = 0; j < 32; ++j) {
                if (((j >> cb) & 1) && !((j >> tb) & 1)) {   // compile-time
                    const int k2 = j | (1 << tb);
                    float t;
                    t = re[j]; re[j] = re[k2]; re[k2] = t;
                    t = im[j]; im[j] = im[k2]; im[k2] = t;
                }
            }
        }

        // w=9: control = local bit 0, target = lane bit 4 (mask 16)
        {
#pragma unroll
            for (int j = 0; j < 32; ++j) {
                if (j & 1) {   // compile-time: only odd locals move; all lanes in-branch
                    const float pr = __shfl_xor_sync(FULLM, re[j], 16);
                    const float pi = __shfl_xor_sync(FULLM, im[j], 16);
                    re[j] = pr; im[j] = pi;
                }
            }
        }
    }

    // ---- Swap-test result: P(1) = 0.5*(1 - sum_{trash=000} |amp|^2)
    // trash wires 7,8,9 -> local bits 2,1,0 -> j in {0,8,16,24}
    float sum = re[0]*re[0] + im[0]*im[0]
              + re[8]*re[8] + im[8]*im[8]
              + re[16]*re[16] + im[16]*im[16]
              + re[24]*re[24] + im[24]*im[24];
#pragma unroll
    for (int off = 16; off; off >>= 1)
        sum += __shfl_xor_sync(FULLM, sum, off);

    if (lane == 0) out[warp_id] = 0.5f * (1.0f - sum);
}

extern "C" void kernel_launch(void* const* d_in, const int* in_sizes, int n_in,
                              void* d_out, int out_size)
{
    const float* features = (const float*)d_in[0];  // [256, 10]
    const float* weights  = (const float*)d_in[1];  // [4, 10]
    float* out = (float*)d_out;                     // [256]
    (void)in_sizes; (void)n_in; (void)out_size;

    // 256 warps = 256 samples; 128 threads/block -> 64 blocks
    qae_kernel<<<64, 128>>>(features, weights, out);
}

// round 3
// speedup vs baseline: 1.6007x; 1.6007x over previous
#include <cuda_runtime.h>

// Quantum autoencoder forward, batch=256, one warp per sample.
//
// R2/R3 changes vs R1:
//  - CNOTs are never applied to data. They are linear maps g -> Cg over GF(2);
//    we track L = (product of CNOTs so far) and apply each RX gate with the
//    pair mask m = L^{-1} e_b instead (RX is symmetric in the pair, so no
//    role disambiguation is needed). All masks are compile-time constants of
//    the fixed circuit, generated by a constexpr function.
//  - Final trash-wire condition (amp index g = Lx has bits 2,1,0 == 0)
//    becomes three compile-time parity checks against rows 0..2 of L.
//  - __sincosf instead of sincosf (error ~5e-7, output is O(0.1..0.5)).
//  - Embedding product state built by doubling (62 muls instead of 320).
//
// Layout: global 10-bit state index x = lane*32 + j.
//   bits 9..5 = lane bits 4..0  (gate pairs across lanes via __shfl_xor_sync)
//   bits 4..0 = local bits 4..0 (gate pairs inside the register array)
// PennyLane wire w (wire 0 = MSB) -> bit (9-w).

#define NUM_Q 10
#define DEPTH 4
#define BATCH 256
#define FULLM 0xFFFFFFFFu

struct Circ {
    unsigned m[DEPTH][NUM_Q];  // m[l][b]: RX pair mask, layer l, bit b (wire 9-b)
    unsigned lrow[3];          // rows 0..2 of final L (trash-bit parities)
};

constexpr Circ make_circ() {
    Circ c{};
    unsigned kcol[NUM_Q] = {};   // columns of K = L^{-1}
    unsigned lr[NUM_Q] = {};     // rows of L
    for (int b = 0; b < NUM_Q; ++b) { kcol[b] = 1u << b; lr[b] = 1u << b; }
    for (int l = 0; l < DEPTH; ++l) {
        // RX gates of layer l see K accumulated from layers 0..l-1
        for (int b = 0; b < NUM_Q; ++b) c.m[l][b] = kcol[b];
        // layer-l ring of CNOT(w, (w+1)%10): control bit 9-w, target bit 9-((w+1)%10)
        for (int w = 0; w < NUM_Q; ++w) {
            const int cb = 9 - w;
            const int tb = (w < 9) ? (8 - w) : 9;
            kcol[cb] ^= kcol[tb];   // K' = K*C : col c += col t
            lr[tb]   ^= lr[cb];     // L' = C*L : row t += row c
        }
    }
    c.lrow[0] = lr[0]; c.lrow[1] = lr[1]; c.lrow[2] = lr[2];
    return c;
}

constexpr Circ CC = make_circ();

// RX with compile-time pair mask M. new_a = c*a - i*s*b (symmetric in pair).
template<unsigned M>
__device__ __forceinline__ void rx_gate(float (&re)[32], float (&im)[32],
                                        float cw, float sw) {
    constexpr unsigned ml = (M >> 5) & 31u;   // lane-xor part
    constexpr int      mj = (int)(M & 31u);   // local-xor part
    if (ml == 0u) {
        // pure local pairing
#pragma unroll
        for (int j = 0; j < 32; ++j) {
            const int k = j ^ mj;
            if (j < k) {
                const float ar = re[j], ai = im[j], br = re[k], bi = im[k];
                re[j] = fmaf(sw, bi, cw * ar);
                im[j] = fmaf(-sw, br, cw * ai);
                re[k] = fmaf(sw, ai, cw * br);
                im[k] = fmaf(-sw, ar, cw * bi);
            }
        }
    } else if (mj == 0) {
        // pure lane pairing: element j pairs with partner lane's element j
#pragma unroll
        for (int j = 0; j < 32; ++j) {
            const float pr = __shfl_xor_sync(FULLM, re[j], ml);
            const float pi = __shfl_xor_sync(FULLM, im[j], ml);
            re[j] = fmaf(sw, pi, cw * re[j]);
            im[j] = fmaf(-sw, pr, cw * im[j]);
        }
    } else {
        // mixed: element j pairs with partner lane's element j^mj.
        // Process canonical pairs {j, j^mj} together: all reads (shfls) of the
        // pair happen before its writes, so no cross-iteration RAW hazard.
#pragma unroll
        for (int j = 0; j < 32; ++j) {
            const int k = j ^ mj;
            if (j < k) {
                const float p0r = __shfl_xor_sync(FULLM, re[k], ml);
                const float p0i = __shfl_xor_sync(FULLM, im[k], ml);
                const float p1r = __shfl_xor_sync(FULLM, re[j], ml);
                const float p1i = __shfl_xor_sync(FULLM, im[j], ml);
                re[j] = fmaf(sw, p0i, cw * re[j]);
                im[j] = fmaf(-sw, p0r, cw * im[j]);
                re[k] = fmaf(sw, p1i, cw * re[k]);
                im[k] = fmaf(-sw, p1r, cw * im[k]);
            }
        }
    }
}

template<int L>
__device__ __forceinline__ void layer(float (&re)[32], float (&im)[32],
                                      const float* __restrict__ weights) {
    float cw[NUM_Q], sw[NUM_Q];
#pragma unroll
    for (int w = 0; w < NUM_Q; ++w)
        __sincosf(0.5f * weights[L * NUM_Q + w], &sw[w], &cw[w]);
    // wire w -> bit 9-w
    rx_gate<CC.m[L][9]>(re, im, cw[0], sw[0]);
    rx_gate<CC.m[L][8]>(re, im, cw[1], sw[1]);
    rx_gate<CC.m[L][7]>(re, im, cw[2], sw[2]);
    rx_gate<CC.m[L][6]>(re, im, cw[3], sw[3]);
    rx_gate<CC.m[L][5]>(re, im, cw[4], sw[4]);
    rx_gate<CC.m[L][4]>(re, im, cw[5], sw[5]);
    rx_gate<CC.m[L][3]>(re, im, cw[6], sw[6]);
    rx_gate<CC.m[L][2]>(re, im, cw[7], sw[7]);
    rx_gate<CC.m[L][1]>(re, im, cw[8], sw[8]);
    rx_gate<CC.m[L][0]>(re, im, cw[9], sw[9]);
}

__global__ void __launch_bounds__(128, 1)
qae_kernel(const float* __restrict__ features,
           const float* __restrict__ weights,
           float* __restrict__ out)
{
    const int warp_id = (blockIdx.x * blockDim.x + threadIdx.x) >> 5;
    const int lane = threadIdx.x & 31;
    if (warp_id >= BATCH) return;

    const float* f = features + warp_id * NUM_Q;

    // ---- embedding: amp[g] = prod_w (bit? sin : cos)(f_w/2) * (-i)^popc(g)
    float fc[NUM_Q], fs[NUM_Q];
#pragma unroll
    for (int w = 0; w < NUM_Q; ++w)
        __sincosf(0.5f * f[w], &fs[w], &fc[w]);

    // lane factor: lane bit b (0..4) corresponds to state bit b+5 = wire 4-b
    float fl = 1.0f;
#pragma unroll
    for (int b = 0; b < 5; ++b)
        fl *= ((lane >> b) & 1) ? fs[4 - b] : fc[4 - b];

    // local magnitudes by doubling over local bits 4..0 (wires 5..9)
    float r[32];
    r[0] = fl;
#pragma unroll
    for (int b = 4; b >= 0; --b) {
        const int w = 9 - b;
        const int st = 1 << b;
#pragma unroll
        for (int j = 0; j < 32; j += 2 * st) {
            r[j + st] = r[j] * fs[w];
            r[j]      = r[j] * fc[w];
        }
    }

    // phase (-i)^popc(x): k = (popc(lane)+popc(j)) & 3
    const int pl = __popc(lane);
    float re[32], im[32];
#pragma unroll
    for (int j = 0; j < 32; ++j) {
        const int kk = (pl + __popc(j)) & 3;   // __popc(j) folds at compile time
        const float v = r[j];
        re[j] = (kk == 0) ? v : ((kk == 2) ? -v : 0.0f);
        im[j] = (kk == 1) ? -v : ((kk == 3) ? v : 0.0f);
    }

    // ---- 4 entangler layers (RX only; CNOTs folded into masks)
    layer<0>(re, im, weights);
    layer<1>(re, im, weights);
    layer<2>(re, im, weights);
    layer<3>(re, im, weights);

    // ---- swap test collapsed: P(aux=1) = 0.5*(1 - sum_{(Lx)&7==0} |amp|^2)
    // parity of bit r of Lx = parity(x & lrow[r]); split lane/local parts.
    const unsigned xl = (unsigned)lane << 5;
    const int code = (__popc(xl & CC.lrow[0]) & 1)
                   | ((__popc(xl & CC.lrow[1]) & 1) << 1)
                   | ((__popc(xl & CC.lrow[2]) & 1) << 2);
    float sum = 0.0f;
#pragma unroll
    for (int j = 0; j < 32; ++j) {
        const int cj = (__popc((unsigned)j & (CC.lrow[0] & 31u)) & 1)
                     | ((__popc((unsigned)j & (CC.lrow[1] & 31u)) & 1) << 1)
                     | ((__popc((unsigned)j & (CC.lrow[2] & 31u)) & 1) << 2);
        if (code == cj)   // lane parity must cancel local parity for all 3 rows
            sum = fmaf(re[j], re[j], fmaf(im[j], im[j], sum));
    }
#pragma unroll
    for (int off = 16; off; off >>= 1)
        sum += __shfl_xor_sync(FULLM, sum, off);

    if (lane == 0) out[warp_id] = 0.5f * (1.0f - sum);
}

extern "C" void kernel_launch(void* const* d_in, const int* in_sizes, int n_in,
                              void* d_out, int out_size)
{
    const float* features = (const float*)d_in[0];  // [256, 10]
    const float* weights  = (const float*)d_in[1];  // [4, 10]
    float* out = (float*)d_out;                     // [256]
    (void)in_sizes; (void)n_in; (void)out_size;

    qae_kernel<<<64, 128>>>(features, weights, out);
}

// round 5
// speedup vs baseline: 1.6281x; 1.0171x over previous
#include <cuda_runtime.h>

// Quantum autoencoder forward, batch=256, one warp per sample.
//
// R4/R5 changes vs R3 (both latency-chain cuts; ncu showed 73% per-warp stall):
//  - every shfl gate is two-phase software-pipelined: a chunk of 32 independent
//    SHFLs into temps, then the dependent FMAs. SHFL latency (26cyc) is covered
//    by the shfl pipeline instead of being exposed per pair.
//  - weight sincos is computed once per warp, spread across lanes (lane i owns
//    weight i; lanes 0-7 also own 32+i), and broadcast per gate with 2 shfls.
//
// Layout: global 10-bit state index x = lane*32 + j.
//   bits 9..5 = lane bits 4..0  (gate pairs across lanes via __shfl_xor_sync)
//   bits 4..0 = local bits 4..0 (gate pairs inside the register array)
// PennyLane wire w (wire 0 = MSB) -> bit (9-w). CNOTs folded into per-gate
// GF(2) pair masks (constexpr), swap test collapsed to trash-000 probability.

#define NUM_Q 10
#define DEPTH 4
#define BATCH 256
#define FULLM 0xFFFFFFFFu

struct Circ {
    unsigned m[DEPTH][NUM_Q];  // m[l][b]: RX pair mask, layer l, bit b (wire 9-b)
    unsigned lrow[3];          // rows 0..2 of final L (trash-bit parities)
};

__host__ __device__ constexpr Circ make_circ() {
    Circ c{};
    unsigned kcol[NUM_Q] = {};   // columns of K = L^{-1}
    unsigned lr[NUM_Q] = {};     // rows of L
    for (int b = 0; b < NUM_Q; ++b) { kcol[b] = 1u << b; lr[b] = 1u << b; }
    for (int l = 0; l < DEPTH; ++l) {
        for (int b = 0; b < NUM_Q; ++b) c.m[l][b] = kcol[b];
        for (int w = 0; w < NUM_Q; ++w) {
            const int cb = 9 - w;
            const int tb = (w < 9) ? (8 - w) : 9;
            kcol[cb] ^= kcol[tb];   // K' = K*C
            lr[tb]   ^= lr[cb];     // L' = C*L
        }
    }
    c.lrow[0] = lr[0]; c.lrow[1] = lr[1]; c.lrow[2] = lr[2];
    return c;
}

constexpr Circ CC = make_circ();

__host__ __device__ constexpr int cmsb(unsigned v) {
    int r = -1;
    while (v) { v >>= 1; ++r; }
    return r;
}

// RX with compile-time pair mask M. new_a = c*a - i*s*b (symmetric in pair).
template<unsigned M>
__device__ __forceinline__ void rx_gate(float (&re)[32], float (&im)[32],
                                        float cw, float sw) {
    constexpr unsigned ml = (M >> 5) & 31u;   // lane-xor part
    constexpr unsigned mj = M & 31u;          // local-xor part
    if constexpr (ml == 0u) {
        // pure local pairing: FMA only, plenty of ILP
#pragma unroll
        for (int j = 0; j < 32; ++j) {
            const int k = j ^ (int)mj;
            if (j < k) {
                const float ar = re[j], ai = im[j], br = re[k], bi = im[k];
                re[j] = fmaf(sw, bi, cw * ar);
                im[j] = fmaf(-sw, br, cw * ai);
                re[k] = fmaf(sw, ai, cw * br);
                im[k] = fmaf(-sw, ar, cw * bi);
            }
        }
    } else if constexpr (mj == 0u) {
        // pure lane pairing: element j pairs with partner lane's element j.
        // Two-phase per 16-element chunk: 32 independent shfls, then FMAs.
#pragma unroll
        for (int base = 0; base < 32; base += 16) {
            float tr[16], ti[16];
#pragma unroll
            for (int t = 0; t < 16; ++t) {
                tr[t] = __shfl_xor_sync(FULLM, re[base + t], ml);
                ti[t] = __shfl_xor_sync(FULLM, im[base + t], ml);
            }
#pragma unroll
            for (int t = 0; t < 16; ++t) {
                re[base + t] = fmaf(sw, ti[t], cw * re[base + t]);
                im[base + t] = fmaf(-sw, tr[t], cw * im[base + t]);
            }
        }
    } else {
        // mixed: element j pairs with partner lane's element j^mj.
        // Enumerate canonical pairs (j < j^mj); two chunks of 8 pairs; within a
        // chunk all 32 shfls (reads of pre-gate values in every lane) precede
        // all writes; chunks touch disjoint element sets -> safe.
        constexpr int h = cmsb(mj);
        constexpr int lo = (1 << h) - 1;
#pragma unroll
        for (int cch = 0; cch < 2; ++cch) {
            float p0r[8], p0i[8], p1r[8], p1i[8];
#pragma unroll
            for (int t = 0; t < 8; ++t) {
                const int tt = cch * 8 + t;
                const int j = ((tt & ~lo) << 1) | (tt & lo);   // bit h clear
                const int k = j ^ (int)mj;
                p0r[t] = __shfl_xor_sync(FULLM, re[k], ml);
                p0i[t] = __shfl_xor_sync(FULLM, im[k], ml);
                p1r[t] = __shfl_xor_sync(FULLM, re[j], ml);
                p1i[t] = __shfl_xor_sync(FULLM, im[j], ml);
            }
#pragma unroll
            for (int t = 0; t < 8; ++t) {
                const int tt = cch * 8 + t;
                const int j = ((tt & ~lo) << 1) | (tt & lo);
                const int k = j ^ (int)mj;
                re[j] = fmaf(sw, p0i[t], cw * re[j]);
                im[j] = fmaf(-sw, p0r[t], cw * im[j]);
                re[k] = fmaf(sw, p1i[t], cw * re[k]);
                im[k] = fmaf(-sw, p1r[t], cw * im[k]);
            }
        }
    }
}

// fetch trig value for global weight index IDX from lane-distributed registers
template<int IDX>
__device__ __forceinline__ float get_trig(float v0, float v1) {
    if constexpr (IDX < 32) return __shfl_sync(FULLM, v0, IDX);
    else                    return __shfl_sync(FULLM, v1, IDX - 32);
}

template<int L, int W>
__device__ __forceinline__ void gate(float (&re)[32], float (&im)[32],
                                     float c0, float s0, float c1, float s1) {
    constexpr int idx = L * NUM_Q + W;
    const float cw = get_trig<idx>(c0, c1);
    const float sw = get_trig<idx>(s0, s1);
    rx_gate<CC.m[L][9 - W]>(re, im, cw, sw);   // wire W -> bit 9-W
}

template<int L>
__device__ __forceinline__ void layer(float (&re)[32], float (&im)[32],
                                      float c0, float s0, float c1, float s1) {
    gate<L, 0>(re, im, c0, s0, c1, s1);
    gate<L, 1>(re, im, c0, s0, c1, s1);
    gate<L, 2>(re, im, c0, s0, c1, s1);
    gate<L, 3>(re, im, c0, s0, c1, s1);
    gate<L, 4>(re, im, c0, s0, c1, s1);
    gate<L, 5>(re, im, c0, s0, c1, s1);
    gate<L, 6>(re, im, c0, s0, c1, s1);
    gate<L, 7>(re, im, c0, s0, c1, s1);
    gate<L, 8>(re, im, c0, s0, c1, s1);
    gate<L, 9>(re, im, c0, s0, c1, s1);
}

__global__ void __launch_bounds__(128, 1)
qae_kernel(const float* __restrict__ features,
           const float* __restrict__ weights,
           float* __restrict__ out)
{
    const int warp_id = (blockIdx.x * blockDim.x + threadIdx.x) >> 5;
    const int lane = threadIdx.x & 31;
    if (warp_id >= BATCH) return;

    const float* f = features + warp_id * NUM_Q;

    // ---- weight trig, lane-distributed (40 values across 32 lanes)
    float c0, s0, c1 = 1.0f, s1 = 0.0f;
    __sincosf(0.5f * weights[lane], &s0, &c0);
    if (lane < DEPTH * NUM_Q - 32) {
        __sincosf(0.5f * weights[32 + lane], &s1, &c1);
    }

    // ---- embedding: amp[g] = prod_w (bit? sin : cos)(f_w/2) * (-i)^popc(g)
    float fc[NUM_Q], fs[NUM_Q];
#pragma unroll
    for (int w = 0; w < NUM_Q; ++w)
        __sincosf(0.5f * f[w], &fs[w], &fc[w]);

    // lane factor: lane bit b (0..4) corresponds to state bit b+5 = wire 4-b
    float fl = 1.0f;
#pragma unroll
    for (int b = 0; b < 5; ++b)
        fl *= ((lane >> b) & 1) ? fs[4 - b] : fc[4 - b];

    // local magnitudes by doubling over local bits 4..0 (wires 5..9)
    float r[32];
    r[0] = fl;
#pragma unroll
    for (int b = 4; b >= 0; --b) {
        const int w = 9 - b;
        const int st = 1 << b;
#pragma unroll
        for (int j = 0; j < 32; j += 2 * st) {
            r[j + st] = r[j] * fs[w];
            r[j]      = r[j] * fc[w];
        }
    }

    // phase (-i)^popc(x)
    const int pl = __popc(lane);
    float re[32], im[32];
#pragma unroll
    for (int j = 0; j < 32; ++j) {
        const int kk = (pl + __popc(j)) & 3;
        const float v = r[j];
        re[j] = (kk == 0) ? v : ((kk == 2) ? -v : 0.0f);
        im[j] = (kk == 1) ? -v : ((kk == 3) ? v : 0.0f);
    }

    // ---- 4 entangler layers (RX only; CNOTs folded into masks)
    layer<0>(re, im, c0, s0, c1, s1);
    layer<1>(re, im, c0, s0, c1, s1);
    layer<2>(re, im, c0, s0, c1, s1);
    layer<3>(re, im, c0, s0, c1, s1);

    // ---- swap test collapsed: P(aux=1) = 0.5*(1 - sum_{(Lx)&7==0} |amp|^2)
    const unsigned xl = (unsigned)lane << 5;
    const int code = (__popc(xl & CC.lrow[0]) & 1)
                   | ((__popc(xl & CC.lrow[1]) & 1) << 1)
                   | ((__popc(xl & CC.lrow[2]) & 1) << 2);
    float sum = 0.0f;
#pragma unroll
    for (int j = 0; j < 32; ++j) {
        const int cj = (__popc((unsigned)j & (CC.lrow[0] & 31u)) & 1)
                     | ((__popc((unsigned)j & (CC.lrow[1] & 31u)) & 1) << 1)
                     | ((__popc((unsigned)j & (CC.lrow[2] & 31u)) & 1) << 2);
        if (code == cj)
            sum = fmaf(re[j], re[j], fmaf(im[j], im[j], sum));
    }
#pragma unroll
    for (int off = 16; off; off >>= 1)
        sum += __shfl_xor_sync(FULLM, sum, off);

    if (lane == 0) out[warp_id] = 0.5f * (1.0f - sum);
}

extern "C" void kernel_launch(void* const* d_in, const int* in_sizes, int n_in,
                              void* d_out, int out_size)
{
    const float* features = (const float*)d_in[0];  // [256, 10]
    const float* weights  = (const float*)d_in[1];  // [4, 10]
    float* out = (float*)d_out;                     // [256]
    (void)in_sizes; (void)n_in; (void)out_size;

    qae_kernel<<<64, 128>>>(features, weights, out);
}

// round 6
// speedup vs baseline: 3.1544x; 1.9375x over previous
#include <cuda_runtime.h>

// Quantum autoencoder forward, batch=256, one warp per sample.
//
// R6: simulate in the X eigenbasis (conjugate circuit by H^10).
//  - RX(th) -> RZ(th) ~ diag(1, e^{i th}) up to global phase: every gate is a
//    pure phase on elements with parity(r . x) = 1; state is a real ANGLE
//    array until the end. 1 FADD per element per gate, zero shfls in gates.
//  - CNOTs (X basis: control/target swapped) remain GF(2)-linear; folded into
//    per-gate parity vectors r = row of accumulated Ltilde, and measurement
//    correlation masks w = columns of Ltilde^{-1} (constexpr).
//  - Embedding in X basis is uniform-magnitude pure phase:
//    phi[y] = 2^-5 exp(i Psi(y)), Psi = sum_w (y_w - 1/2) f_w -> angle init.
//  - Swap test: P(aux=1) = .5(1 - sum), sum = <phi| prod_r (1+X_{e_r})/2 |phi>
//    = (1/8192)(1024 + sum_{7 nonzero S} R_S), R_S = sum_x Re(conj e[x] e[x^w_S]).
//
// Layout: x = lane*32 + j; bits 9..5 = lane bits, bits 4..0 = local bits.
// Wire w (PennyLane MSB-first) -> bit 9-w.

#define NUM_Q 10
#define DEPTH 4
#define BATCH 256
#define FULLM 0xFFFFFFFFu

struct CircX {
    unsigned r[DEPTH][NUM_Q];  // r[l][b]: parity vector for RZ on bit b, layer l
    unsigned wv[8];            // wv[s]: correlation mask for subset s of trash bits
};

__host__ __device__ constexpr CircX make_circx() {
    CircX c{};
    unsigned lr[NUM_Q] = {};   // rows of Ltilde
    unsigned kc[NUM_Q] = {};   // columns of Ktilde = Ltilde^{-1}
    for (int b = 0; b < NUM_Q; ++b) { lr[b] = 1u << b; kc[b] = 1u << b; }
    for (int l = 0; l < DEPTH; ++l) {
        for (int b = 0; b < NUM_Q; ++b) c.r[l][b] = lr[b];
        // actual CNOT(w,(w+1)%10): Z-basis control bit cb=9-w, target tb.
        // X basis: index map y_cb ^= y_tb  => Ltilde row cb ^= row tb,
        //                                     Ktilde col tb ^= col cb.
        for (int w = 0; w < NUM_Q; ++w) {
            const int cb = 9 - w;
            const int tb = (w < 9) ? (8 - w) : 9;
            lr[cb] ^= lr[tb];
            kc[tb] ^= kc[cb];
        }
    }
    for (unsigned s = 0; s < 8; ++s) {
        unsigned v = 0;
        for (int r2 = 0; r2 < 3; ++r2)
            if ((s >> r2) & 1) v ^= kc[r2];
        c.wv[s] = v;
    }
    return c;
}

constexpr CircX CX = make_circx();

// ---- gate loop: ang[j] += th * parity(r . x), folded as a0/a1 select ----
template<int G>
__device__ __forceinline__ void gates(float (&ang)[32], float v0, float v1, int lane) {
    if constexpr (G < DEPTH * NUM_Q) {
        constexpr int l = G / NUM_Q;
        constexpr int w = G % NUM_Q;
        constexpr unsigned r = CX.r[l][9 - w];
        constexpr unsigned rl = (r >> 5) & 31u;
        constexpr unsigned rj = r & 31u;
        float th;
        if constexpr (G < 32) th = __shfl_sync(FULLM, v0, G);
        else                  th = __shfl_sync(FULLM, v1, G - 32);
        float a0, a1;
        if constexpr (rl != 0u) {
            const int bl = __popc((unsigned)lane & rl) & 1;
            a0 = bl ? th : 0.0f;   // th * laneparity
            a1 = th - a0;          // th * (1 - laneparity)
        } else {
            a0 = 0.0f; a1 = th;
        }
#pragma unroll
        for (int j = 0; j < 32; ++j)
            ang[j] += ((__popc((unsigned)j & rj) & 1) ? a1 : a0);  // compile-time sel
        gates<G + 1>(ang, v0, v1, lane);
    }
}

// ---- measurement correlations R_S, accumulated into 4 rotating accs ----
template<int S>
__device__ __forceinline__ void correlate(const float (&re)[32], const float (&im)[32],
                                          float (&acc)[4]) {
    if constexpr (S < 8) {
        constexpr unsigned W = CX.wv[S];
        constexpr unsigned wl = (W >> 5) & 31u;
        constexpr unsigned wj = W & 31u;
        if constexpr (wl == 0u) {
#pragma unroll
            for (int j = 0; j < 32; ++j) {
                const int k = j ^ (int)wj;
                acc[j & 3] = fmaf(re[j], re[k], acc[j & 3]);
                acc[(j + 2) & 3] = fmaf(im[j], im[k], acc[(j + 2) & 3]);
            }
        } else {
            // partner element: lane^wl, local j^wj. reads only -> chunk freely.
#pragma unroll
            for (int base = 0; base < 32; base += 16) {
                float pr[16], pi[16];
#pragma unroll
                for (int t = 0; t < 16; ++t) {
                    const int k = (base + t) ^ (int)wj;
                    pr[t] = __shfl_xor_sync(FULLM, re[k], wl);
                    pi[t] = __shfl_xor_sync(FULLM, im[k], wl);
                }
#pragma unroll
                for (int t = 0; t < 16; ++t) {
                    const int j = base + t;
                    acc[j & 3] = fmaf(re[j], pr[t], acc[j & 3]);
                    acc[(j + 2) & 3] = fmaf(im[j], pi[t], acc[(j + 2) & 3]);
                }
            }
        }
        correlate<S + 1>(re, im, acc);
    }
}

__global__ void __launch_bounds__(128, 1)
qae_kernel(const float* __restrict__ features,
           const float* __restrict__ weights,
           float* __restrict__ out)
{
    const int warp_id = (blockIdx.x * blockDim.x + threadIdx.x) >> 5;
    const int lane = threadIdx.x & 31;
    if (warp_id >= BATCH) return;

    const float* f = features + warp_id * NUM_Q;

    // weights lane-distributed (40 values): raw angles, no trig needed
    const float v0 = weights[lane];
    const float v1 = (lane < DEPTH * NUM_Q - 32) ? weights[32 + lane] : 0.0f;

    float fw[NUM_Q];
#pragma unroll
    for (int w = 0; w < NUM_Q; ++w) fw[w] = f[w];

    // ---- embedding angles: Psi(x) = -F/2 + sum_{set wires} f_w
    float F = 0.0f;
#pragma unroll
    for (int w = 0; w < NUM_Q; ++w) F += fw[w];
    float A = -0.5f * F;
#pragma unroll
    for (int w = 0; w < 5; ++w)               // lane bit (4-w) <-> wire w
        if ((lane >> (4 - w)) & 1) A += fw[w];

    float ang[32];
    ang[0] = A;
#pragma unroll
    for (int b = 4; b >= 0; --b) {            // local bit b <-> wire 9-b
        const int st = 1 << b;
#pragma unroll
        for (int j = 0; j < 32; j += 2 * st)
            ang[j + st] = ang[j] + fw[9 - b];
    }

    // ---- 40 diagonal gates: one FADD per element each
    gates<0>(ang, v0, v1, lane);

    // ---- materialize unit phasors
    float re[32], im[32];
#pragma unroll
    for (int j = 0; j < 32; ++j)
        __sincosf(ang[j], &im[j], &re[j]);

    // ---- 7 correlations
    float acc[4] = {0.0f, 0.0f, 0.0f, 0.0f};
    correlate<1>(re, im, acc);
    float tot = (acc[0] + acc[1]) + (acc[2] + acc[3]);
#pragma unroll
    for (int off = 16; off; off >>= 1)
        tot += __shfl_xor_sync(FULLM, tot, off);

    // sum = (1024 + tot)/8192 ; P = 0.5*(1 - sum)
    if (lane == 0)
        out[warp_id] = 0.5f - (1024.0f + tot) * 6.103515625e-05f;
}

extern "C" void kernel_launch(void* const* d_in, const int* in_sizes, int n_in,
                              void* d_out, int out_size)
{
    const float* features = (const float*)d_in[0];  // [256, 10]
    const float* weights  = (const float*)d_in[1];  // [4, 10]
    float* out = (float*)d_out;                     // [256]
    (void)in_sizes; (void)n_in; (void)out_size;

    qae_kernel<<<64, 128>>>(features, weights, out);
}

// round 7
// speedup vs baseline: 3.9722x; 1.2593x over previous
#include <cuda_runtime.h>

// Quantum autoencoder forward, batch=256. R7: one CTA (256 threads) per sample.
//
// X-eigenbasis simulation (verified R6): every RX is a diagonal phase, state is
// a real angle per element until the end; CNOTs folded into constexpr GF(2)
// parity vectors; swap test = 7 X-correlations.
//   ang[x] = Psi_emb(x) + sum_G theta_G * parity(r_G . x)
//   P(aux=1) = 0.5*(1 - (1024 + sum_{S!=0} R_S)/8192),
//   R_S = sum_x ( re[x]*re[x^w_S] + im[x]*im[x^w_S] ).
//
// Element-parallel: thread t owns elements x = 4t..4t+3 (low 2 bits compile
// time). Gates: 1 runtime popc-parity per gate + compile-time select per
// element. Correlations via shared-memory staging: partner block x0^(W&~3) is
// float4-aligned; low-2-bit part of W is a compile-time component permute.

#define NUM_Q 10
#define DEPTH 4
#define BATCH 256
#define TPB 256
#define FULLM 0xFFFFFFFFu

struct CircX {
    unsigned r[DEPTH][NUM_Q];  // parity vector for the RZ from (layer l, wire w) at bit b
    unsigned wv[8];            // correlation mask for subset s of trash bits
};

__host__ __device__ constexpr CircX make_circx() {
    CircX c{};
    unsigned lr[NUM_Q] = {};   // rows of Ltilde
    unsigned kc[NUM_Q] = {};   // columns of Ktilde = Ltilde^{-1}
    for (int b = 0; b < NUM_Q; ++b) { lr[b] = 1u << b; kc[b] = 1u << b; }
    for (int l = 0; l < DEPTH; ++l) {
        for (int b = 0; b < NUM_Q; ++b) c.r[l][b] = lr[b];
        for (int w = 0; w < NUM_Q; ++w) {
            const int cb = 9 - w;
            const int tb = (w < 9) ? (8 - w) : 9;
            lr[cb] ^= lr[tb];
            kc[tb] ^= kc[cb];
        }
    }
    for (unsigned s = 0; s < 8; ++s) {
        unsigned v = 0;
        for (int r2 = 0; r2 < 3; ++r2)
            if ((s >> r2) & 1) v ^= kc[r2];
        c.wv[s] = v;
    }
    return c;
}

constexpr CircX CX = make_circx();

template<int E>
__device__ __forceinline__ float f4c(const float4& v) {
    if constexpr (E == 0) return v.x;
    else if constexpr (E == 1) return v.y;
    else if constexpr (E == 2) return v.z;
    else return v.w;
}

// ---- 40 diagonal gates on this thread's 4 elements ----
template<int G>
__device__ __forceinline__ void gates(float (&ang)[4],
                                      const float* __restrict__ wts,
                                      unsigned x0) {
    if constexpr (G < DEPTH * NUM_Q) {
        constexpr unsigned r = CX.r[G / NUM_Q][9 - (G % NUM_Q)];
        const float th = __ldg(wts + G);
        const int p = __popc(x0 & (r & ~3u)) & 1;       // runtime parity (bits 2..9)
        const float a0 = p ? th : 0.0f;                 // contribution when elem-parity even
        const float a1 = th - a0;                       // contribution when elem-parity odd
#pragma unroll
        for (int e = 0; e < 4; ++e) {
            constexpr unsigned rlo = r & 3u;
            const int pe = __popc((unsigned)e & rlo) & 1;   // folds per unrolled e
            ang[e] += pe ? a1 : a0;
        }
        gates<G + 1>(ang, wts, x0);
    }
}

// ---- 7 correlations via shared-memory partners ----
template<int S>
__device__ __forceinline__ void correlate(const float (&re)[4], const float (&im)[4],
                                          const float* s_re, const float* s_im,
                                          unsigned x0, float& acc) {
    if constexpr (S < 8) {
        constexpr unsigned W = CX.wv[S];
        constexpr unsigned whi = W & ~3u;
        constexpr unsigned wlo = W & 3u;
        const float4 pr = *reinterpret_cast<const float4*>(s_re + (x0 ^ whi));
        const float4 pi = *reinterpret_cast<const float4*>(s_im + (x0 ^ whi));
        acc = fmaf(re[0], f4c<(0 ^ wlo)>(pr), acc);
        acc = fmaf(im[0], f4c<(0 ^ wlo)>(pi), acc);
        acc = fmaf(re[1], f4c<(1 ^ wlo)>(pr), acc);
        acc = fmaf(im[1], f4c<(1 ^ wlo)>(pi), acc);
        acc = fmaf(re[2], f4c<(2 ^ wlo)>(pr), acc);
        acc = fmaf(im[2], f4c<(2 ^ wlo)>(pi), acc);
        acc = fmaf(re[3], f4c<(3 ^ wlo)>(pr), acc);
        acc = fmaf(im[3], f4c<(3 ^ wlo)>(pi), acc);
        correlate<S + 1>(re, im, s_re, s_im, x0, acc);
    }
}

__global__ void __launch_bounds__(TPB, 2)
qae_kernel(const float* __restrict__ features,
           const float* __restrict__ weights,
           float* __restrict__ out)
{
    __shared__ float s_re[1024];
    __shared__ float s_im[1024];
    __shared__ float s_wsum[TPB / 32];

    const int tid = threadIdx.x;
    const unsigned x0 = (unsigned)tid << 2;
    const float* f = features + blockIdx.x * NUM_Q;

    // features (uniform across block -> broadcast loads)
    float fw[NUM_Q];
#pragma unroll
    for (int w = 0; w < NUM_Q; ++w) fw[w] = __ldg(f + w);

    // embedding angle: Psi(x) = -F/2 + sum_{bits set in x} f_{9-bit}
    float F = 0.0f;
#pragma unroll
    for (int w = 0; w < NUM_Q; ++w) F += fw[w];
    float base = -0.5f * F;
#pragma unroll
    for (int b = 2; b < 10; ++b)
        if ((x0 >> b) & 1) base += fw[9 - b];

    float ang[4];
    ang[0] = base;
    ang[1] = base + fw[9];           // local bit 0 <-> wire 9
    ang[2] = base + fw[8];           // local bit 1 <-> wire 8
    ang[3] = base + fw[8] + fw[9];

    // 40 diagonal gates
    gates<0>(ang, weights, x0);

    // materialize unit phasors and stage in smem
    float re[4], im[4];
#pragma unroll
    for (int e = 0; e < 4; ++e)
        __sincosf(ang[e], &im[e], &re[e]);

    *reinterpret_cast<float4*>(s_re + x0) = make_float4(re[0], re[1], re[2], re[3]);
    *reinterpret_cast<float4*>(s_im + x0) = make_float4(im[0], im[1], im[2], im[3]);
    __syncthreads();

    // 7 correlations
    float acc = 0.0f;
    correlate<1>(re, im, s_re, s_im, x0, acc);

    // block reduction
#pragma unroll
    for (int off = 16; off; off >>= 1)
        acc += __shfl_xor_sync(FULLM, acc, off);
    if ((tid & 31) == 0) s_wsum[tid >> 5] = acc;
    __syncthreads();
    if (tid < TPB / 32) {
        float v = s_wsum[tid];
#pragma unroll
        for (int off = (TPB / 64); off; off >>= 1)
            v += __shfl_xor_sync(FULLM, v, off);
        if (tid == 0)
            out[blockIdx.x] = 0.5f - (1024.0f + v) * 6.103515625e-05f;
    }
}

extern "C" void kernel_launch(void* const* d_in, const int* in_sizes, int n_in,
                              void* d_out, int out_size)
{
    const float* features = (const float*)d_in[0];  // [256, 10]
    const float* weights  = (const float*)d_in[1];  // [4, 10]
    float* out = (float*)d_out;                     // [256]
    (void)in_sizes; (void)n_in; (void)out_size;

    qae_kernel<<<BATCH, TPB>>>(features, weights, out);
}